// round 14
// baseline (speedup 1.0000x reference)
#include <cuda_runtime.h>
#include <cuda_bf16.h>
#include <math.h>
#include <stdint.h>

#define BATCH 2
#define SEQ   4096
#define DIM   1024
#define NH    16
#define DK    64
#define WIN   256
#define HALF  (DIM/2)
#define MROWS (BATCH*SEQ)      // 8192
#define K2    (2*DIM)          // 2048 storage: [hi|lo]
// logical GEMM K = 3*DIM via chunk remap: [hiA|loA|hiA] x [hiW|hiW|loW]

// ---------------------------------------------------------------------------
// Scratch (allocation-free: __device__ globals)
// ---------------------------------------------------------------------------
__device__ float g_vp[MROWS*DIM];
__device__ float2 g_tbl[SEQ*HALF];                  // cos/sin table
__device__ __nv_bfloat16 g_qb [(size_t)MROWS*K2];
__device__ __nv_bfloat16 g_kb [(size_t)MROWS*K2];
__device__ __nv_bfloat16 g_vb [(size_t)MROWS*K2];
__device__ __nv_bfloat16 g_aob[(size_t)MROWS*K2];
__device__ __nv_bfloat16 g_wqb[(size_t)DIM*K2];
__device__ __nv_bfloat16 g_wkb[(size_t)DIM*K2];
__device__ __nv_bfloat16 g_wvb[(size_t)DIM*K2];
__device__ __nv_bfloat16 g_wob[(size_t)DIM*K2];
// per-head bf16 hi/lo buffers for attention
__device__ __nv_bfloat16 g_qh [(size_t)MROWS*DIM];
__device__ __nv_bfloat16 g_ql [(size_t)MROWS*DIM];
__device__ __nv_bfloat16 g_kh [(size_t)MROWS*DIM];
__device__ __nv_bfloat16 g_kl [(size_t)MROWS*DIM];
__device__ __nv_bfloat16 g_vth[(size_t)MROWS*DIM];  // V^T per head
__device__ __nv_bfloat16 g_vtl[(size_t)MROWS*DIM];

// ---------------------------------------------------------------------------
// Baseline-ISA helpers: cp.async / ldmatrix / mma.sync (no tcgen05).
// ---------------------------------------------------------------------------
__device__ __forceinline__ uint32_t smem_u32(const void* p) {
    uint32_t a;
    asm("{ .reg .u64 t; cvta.to.shared.u64 t, %1; cvt.u32.u64 %0, t; }"
        : "=r"(a) : "l"(p));
    return a;
}
__device__ __forceinline__ void cp16(uint32_t s, const void* g) {
    asm volatile("cp.async.cg.shared.global [%0], [%1], 16;" :: "r"(s), "l"(g));
}
#define CP_COMMIT() asm volatile("cp.async.commit_group;" ::: "memory")
#define CP_WAIT1()  asm volatile("cp.async.wait_group 1;"  ::: "memory")
#define CP_WAIT0()  asm volatile("cp.async.wait_group 0;"  ::: "memory")

__device__ __forceinline__ void ldsm_x4(uint32_t* r, uint32_t addr) {
    asm volatile("ldmatrix.sync.aligned.m8n8.x4.shared.b16 {%0,%1,%2,%3}, [%4];"
                 : "=r"(r[0]), "=r"(r[1]), "=r"(r[2]), "=r"(r[3]) : "r"(addr));
}
__device__ __forceinline__ void mma16816(float* c, const uint32_t* a,
                                         uint32_t b0, uint32_t b1) {
    asm volatile(
        "mma.sync.aligned.m16n8k16.row.col.f32.bf16.bf16.f32 "
        "{%0,%1,%2,%3}, {%4,%5,%6,%7}, {%8,%9}, {%0,%1,%2,%3};"
        : "+f"(c[0]), "+f"(c[1]), "+f"(c[2]), "+f"(c[3])
        : "r"(a[0]), "r"(a[1]), "r"(a[2]), "r"(a[3]), "r"(b0), "r"(b1));
}
static __device__ __forceinline__ uint32_t sw128(uint32_t off) {
    return off ^ ((off >> 3) & 0x70);
}
__device__ __forceinline__ uint32_t pack2bf(float a, float b) {
    __nv_bfloat162 t = __floats2bfloat162_rn(a, b);
    return *reinterpret_cast<uint32_t*>(&t);
}

// ---------------------------------------------------------------------------
// fp32 -> bf16 hi/lo split, multi-tensor, optional exact power-of-2 scale.
// dst row = [hi(0..K) | lo(K..2K)]
// ---------------------------------------------------------------------------
struct SplitArgs {
    const float*   src[4];
    __nv_bfloat16* dst[4];
    float          scl[4];
};

__global__ __launch_bounds__(256) void split_multi(SplitArgs a, int total, int K)
{
    const float* __restrict__ src = a.src[blockIdx.z];
    __nv_bfloat16* __restrict__ dst = a.dst[blockIdx.z];
    const float scl = a.scl[blockIdx.z];

    int i4 = blockIdx.x * blockDim.x + threadIdx.x;
    if (i4 * 4 >= total) return;
    int idx = i4 * 4;
    int row = idx / K;
    int col = idx % K;

    float4 x = *(const float4*)(src + idx);
    x.x *= scl; x.y *= scl; x.z *= scl; x.w *= scl;
    __nv_bfloat16 h0 = __float2bfloat16(x.x);
    __nv_bfloat16 h1 = __float2bfloat16(x.y);
    __nv_bfloat16 h2 = __float2bfloat16(x.z);
    __nv_bfloat16 h3 = __float2bfloat16(x.w);
    __nv_bfloat16 l0 = __float2bfloat16(x.x - __bfloat162float(h0));
    __nv_bfloat16 l1 = __float2bfloat16(x.y - __bfloat162float(h1));
    __nv_bfloat16 l2 = __float2bfloat16(x.z - __bfloat162float(h2));
    __nv_bfloat16 l3 = __float2bfloat16(x.w - __bfloat162float(h3));

    size_t base = (size_t)row * (2 * K);
    __nv_bfloat162* d0 = (__nv_bfloat162*)(dst + base + col);
    d0[0] = __nv_bfloat162(h0, h1); d0[1] = __nv_bfloat162(h2, h3);
    __nv_bfloat162* d1 = (__nv_bfloat162*)(dst + base + K + col);
    d1[0] = __nv_bfloat162(l0, l1); d1[1] = __nv_bfloat162(l2, l3);
}

// ---------------------------------------------------------------------------
// Tensor-core GEMM via mma.sync (R10/R12 measured-best core):
// CTA 128x128, 8 warps (2x4), warp tile 64x32, logical K=3072 remapped into
// [hi|lo] storage, 3-stage cp.async pipeline, fragment double-buffering,
// 2 CTAs/SM.
// mode 1 (q/k): B rows pair-interleaved (e, e+512, e+1, e+513, ...) so each
// RoPE pair lands in ONE thread's accumulator regs 0/1 (and 2/3). Epilogue
// is register-only: rotate + bf16 hi/lo store to per-head layout. No smem,
// no extra syncs. mode 0: plain fp32 (+bias) store.
// ---------------------------------------------------------------------------
#define TM 128
#define TN 128
#define KC 64
#define NCHUNK ((3*DIM)/KC)    // 48
#define SMBUF  32768           // 16KB A + 16KB B per stage
#define DYN_SMEM (3*SMBUF + 1024)

struct TCArgs {
    const __nv_bfloat16* A[3];
    const __nv_bfloat16* W[3];
    float*               C[3];
    const float*         bias[3];
    __nv_bfloat16*       H[3];
    __nv_bfloat16*       L[3];
    const float2*        tbl;
    int                  mode[3];   // 0 plain, 1 rope
};

__device__ __forceinline__ void cp_chunk(
    uint32_t smA, uint32_t smB,
    const __nv_bfloat16* __restrict__ A, const __nv_bfloat16* __restrict__ W,
    int m0, int n0, int kcol, int tid, int rope)
{
    // remap logical k (0..3071) into [hi|lo] storage (0..2047)
    const int ka = (kcol < 2048) ? kcol : kcol - 2048;  // A: hi,lo,hi
    const int kw = (kcol < 1024) ? kcol : kcol - 1024;  // W: hi,hi,lo
#pragma unroll
    for (int i = 0; i < 4; i++) {
        int v = tid + i * 256;
        int row = v >> 3, vc = v & 7;
        cp16(smA + sw128(row * 128 + vc * 16),
             A + (size_t)(m0 + row) * K2 + ka + vc * 8);
    }
#pragma unroll
    for (int i = 0; i < 4; i++) {
        int v = tid + i * 256;
        int row = v >> 3, vc = v & 7;
        // rope: pair-interleave rows -> W row e=(n0/2 + row/2), +512 if odd
        int wrow = rope ? ((n0 >> 1) + (row >> 1) + (row & 1) * 512)
                        : (n0 + row);
        cp16(smB + sw128(row * 128 + vc * 16),
             W + (size_t)wrow * K2 + kw + vc * 8);
    }
}

__global__ __launch_bounds__(256, 2) void mma_gemm(TCArgs args, int N)
{
    extern __shared__ char smraw[];
    const uint32_t sb0 = smem_u32(smraw);
    const uint32_t sb  = (sb0 + 1023u) & ~1023u;

    const int z = blockIdx.z;
    const __nv_bfloat16* __restrict__ A = args.A[z];
    const __nv_bfloat16* __restrict__ W = args.W[z];
    const int mode = args.mode[z];
    const int rope = (mode != 0);

    const int tid  = threadIdx.x;
    const int wid  = tid >> 5;
    const int lane = tid & 31;
    const int wm   = wid & 1;
    const int wn   = wid >> 1;
    const int m0 = blockIdx.y * TM;
    const int n0 = blockIdx.x * TN;

    const int a_row = lane & 15;
    const int a_kb  = (lane >> 4) * 16;
    const int b_row = (lane & 7) + ((lane >> 4) * 8);
    const int b_kb  = ((lane >> 3) & 1) * 16;

    float acc[4][4][4];
#pragma unroll
    for (int i = 0; i < 4; i++)
#pragma unroll
        for (int j = 0; j < 4; j++)
#pragma unroll
            for (int t = 0; t < 4; t++) acc[i][j][t] = 0.f;

    // prologue: chunks 0,1 -> stages 0,1
    cp_chunk(sb, sb + 16384, A, W, m0, n0, 0, tid, rope);
    CP_COMMIT();
    cp_chunk(sb + SMBUF, sb + SMBUF + 16384, A, W, m0, n0, KC, tid, rope);
    CP_COMMIT();

    uint32_t af[2][4][4], bf2[2][8];

    for (int i = 0; i < NCHUNK; i++) {
        if (i + 1 < NCHUNK) { CP_WAIT1(); } else { CP_WAIT0(); }
        __syncthreads();                              // chunk i visible to all

        if (i + 2 < NCHUNK) {
            const uint32_t st = sb + ((i + 2) % 3) * SMBUF;
            cp_chunk(st, st + 16384, A, W, m0, n0, (i + 2) * KC, tid, rope);
            CP_COMMIT();
        }

        const uint32_t smA = sb + (i % 3) * SMBUF;
        const uint32_t smB = smA + 16384;

        // frags for ks=0
        {
#pragma unroll
            for (int mt = 0; mt < 4; mt++) {
                uint32_t off = (uint32_t)(wm * 64 + mt * 16 + a_row) * 128 + a_kb;
                ldsm_x4(af[0][mt], smA + sw128(off));
            }
#pragma unroll
            for (int bt = 0; bt < 2; bt++) {
                uint32_t off = (uint32_t)(wn * 32 + bt * 16 + b_row) * 128 + b_kb;
                ldsm_x4(bf2[0] + bt * 4, smB + sw128(off));
            }
        }
#pragma unroll
        for (int ks = 0; ks < 4; ks++) {
            const int cur = ks & 1;
            if (ks < 3) {
                const int nxt = cur ^ 1;
#pragma unroll
                for (int mt = 0; mt < 4; mt++) {
                    uint32_t off = (uint32_t)(wm * 64 + mt * 16 + a_row) * 128
                                 + (ks + 1) * 32 + a_kb;
                    ldsm_x4(af[nxt][mt], smA + sw128(off));
                }
#pragma unroll
                for (int bt = 0; bt < 2; bt++) {
                    uint32_t off = (uint32_t)(wn * 32 + bt * 16 + b_row) * 128
                                 + (ks + 1) * 32 + b_kb;
                    ldsm_x4(bf2[nxt] + bt * 4, smB + sw128(off));
                }
            }
#pragma unroll
            for (int mt = 0; mt < 4; mt++)
#pragma unroll
                for (int nt = 0; nt < 4; nt++) {
                    const int bi = (nt >> 1) * 4 + (nt & 1) * 2;
                    mma16816(acc[mt][nt], af[cur][mt], bf2[cur][bi], bf2[cur][bi + 1]);
                }
        }
    }

    if (mode == 0) {
        float* __restrict__ C = args.C[z];
        const float* bias = args.bias[z];
        const int rbase = m0 + wm * 64 + (lane >> 2);
        const int cbase = n0 + wn * 32 + 2 * (lane & 3);
#pragma unroll
        for (int mt = 0; mt < 4; mt++) {
#pragma unroll
            for (int nt = 0; nt < 4; nt++) {
                const int r = rbase + mt * 16;
                const int c = cbase + nt * 8;
                float2 v0 = { acc[mt][nt][0], acc[mt][nt][1] };
                float2 v1 = { acc[mt][nt][2], acc[mt][nt][3] };
                if (bias) {
                    v0.x += bias[c]; v0.y += bias[c + 1];
                    v1.x += bias[c]; v1.y += bias[c + 1];
                }
                *(float2*)(C + (size_t)r * N + c)       = v0;
                *(float2*)(C + (size_t)(r + 8) * N + c) = v1;
            }
        }
        return;
    }

    // ---- register-only RoPE + per-head hi/lo epilogue ----
    // Thread's acc[mt][nt][0/1] = cols (c, c+1) = RoPE pair (e, e+512) for
    // e = bx*64 + d, d = wn*16 + (lane&3) + nt*4. Rows: r and r+8 ([2/3]).
    __nv_bfloat16* __restrict__ H = args.H[z];
    __nv_bfloat16* __restrict__ L = args.L[z];
    const float2* __restrict__ tbl = args.tbl;
    const int h1 = blockIdx.x;           // head for first half
    const int h2 = blockIdx.x + 8;       // head for second half (+512)
    const int rl = m0 + wm * 64 + (lane >> 2);
    const int dbase = wn * 16 + (lane & 3);
    const float2* tcol = tbl + (size_t)blockIdx.x * 64;   // freq base bx*64

#pragma unroll
    for (int mt = 0; mt < 4; mt++) {
#pragma unroll
        for (int half = 0; half < 2; half++) {
            const int grow = rl + mt * 16 + half * 8;
            const int s    = grow & (SEQ - 1);
            const int bidx = grow >> 12;
            const size_t base1 = ((size_t)(bidx * NH + h1) * SEQ + s) * DK;
            const size_t base2 = ((size_t)(bidx * NH + h2) * SEQ + s) * DK;
            const float2* trow = tcol + (size_t)s * HALF;
#pragma unroll
            for (int nt = 0; nt < 4; nt++) {
                const int d = dbase + nt * 4;
                float2 t = trow[d];
                const float x1 = acc[mt][nt][half * 2];
                const float x2 = acc[mt][nt][half * 2 + 1];
                const float v1 = x1 * t.x - x2 * t.y;
                const float v2 = x1 * t.y + x2 * t.x;
                __nv_bfloat16 hb1 = __float2bfloat16(v1);
                __nv_bfloat16 hb2 = __float2bfloat16(v2);
                H[base1 + d] = hb1;
                L[base1 + d] = __float2bfloat16(v1 - __bfloat162float(hb1));
                H[base2 + d] = hb2;
                L[base2 + d] = __float2bfloat16(v2 - __bfloat162float(hb2));
            }
        }
    }
}

// ---------------------------------------------------------------------------
// RoPE cos/sin table
// ---------------------------------------------------------------------------
#define RPT 16
__global__ __launch_bounds__(512) void rope_table(float2* __restrict__ tbl)
{
    const int e    = threadIdx.x;
    const int pgrp = blockIdx.x;

    const double inv = exp(-((double)e / (double)HALF) * 9.2103403719761827);

#pragma unroll 4
    for (int i = 0; i < RPT; i++) {
        const int pos = pgrp * RPT + i;
        const double ang = (double)pos * inv;
        const double kq  = rint(ang * 0.15915494309189533);
        const float  r   = (float)(ang - kq * 6.2831853071795865);
        float s, c;
        sincosf(r, &s, &c);
        tbl[(size_t)pos * HALF + e] = make_float2(c, s);
    }
}

// ---------------------------------------------------------------------------
// convert_v: vp -> V^T bf16 hi/lo
// ---------------------------------------------------------------------------
__global__ __launch_bounds__(256) void convert_v(
    const float* __restrict__ vp,
    __nv_bfloat16* __restrict__ vth, __nv_bfloat16* __restrict__ vtl)
{
    __shared__ float tile[128][65];
    const int st = blockIdx.x, hh = blockIdx.y, b = blockIdx.z;
    const int tid = threadIdx.x;

#pragma unroll
    for (int i = 0; i < 8; i++) {
        int v = tid + i * 256;
        int s = v >> 4, dseg = v & 15;
        float4 x = *(const float4*)(vp
            + ((size_t)(b * SEQ) + st * 128 + s) * DIM + hh * 64 + dseg * 4);
        tile[s][dseg*4+0] = x.x; tile[s][dseg*4+1] = x.y;
        tile[s][dseg*4+2] = x.z; tile[s][dseg*4+3] = x.w;
    }
    __syncthreads();

#pragma unroll
    for (int i = 0; i < 4; i++) {
        int v = tid + i * 256;
        int d = v >> 4, kseg = v & 15;
        __nv_bfloat16 hi8[8], lo8[8];
#pragma unroll
        for (int j = 0; j < 8; j++) {
            float x = tile[kseg * 8 + j][d];
            hi8[j] = __float2bfloat16(x);
            lo8[j] = __float2bfloat16(x - __bfloat162float(hi8[j]));
        }
        size_t dst = (((size_t)(b * NH + hh)) * DK + d) * SEQ + st * 128 + kseg * 8;
        *(uint4*)(vth + dst) = *(uint4*)hi8;
        *(uint4*)(vtl + dst) = *(uint4*)lo8;
    }
}

// ---------------------------------------------------------------------------
// Flash attention on tensor cores; epilogue writes aob as bf16 [hi|lo].
// ---------------------------------------------------------------------------
#define ATT_SMK0 32768
#define ATT_KBUF 32768
#define ATT_SMV0 98304
#define ATT_VBUF 34816
#define ATT_SMEM (167936 + 1024)

__device__ __forceinline__ void attn_load_kv(
    uint32_t sb, int buf,
    const __nv_bfloat16* __restrict__ kh, const __nv_bfloat16* __restrict__ kl,
    const __nv_bfloat16* __restrict__ vth, const __nv_bfloat16* __restrict__ vtl,
    size_t bh, int kbase, int tid)
{
    const uint32_t kdst = sb + ATT_SMK0 + buf * ATT_KBUF;
    const size_t krow0 = bh * SEQ + kbase;
#pragma unroll
    for (int i = 0; i < 4; i++) {
        int v = tid + i * 256; int row = v >> 3, seg = v & 7;
        uint32_t off = sw128((uint32_t)(row * 128 + seg * 16));
        cp16(kdst + off,         kh + (krow0 + row) * DK + seg * 8);
        cp16(kdst + 16384 + off, kl + (krow0 + row) * DK + seg * 8);
    }
    const uint32_t vdst = sb + ATT_SMV0 + buf * ATT_VBUF;
    const size_t vrow0 = bh * DK;
#pragma unroll
    for (int i = 0; i < 4; i++) {
        int v = tid + i * 256; int d = v >> 4, seg = v & 15;
        uint32_t off = (uint32_t)(d * 272 + seg * 16);
        cp16(vdst + off,         vth + (vrow0 + d) * SEQ + kbase + seg * 8);
        cp16(vdst + 17408 + off, vtl + (vrow0 + d) * SEQ + kbase + seg * 8);
    }
}

__global__ __launch_bounds__(256, 1) void attn2(
    const __nv_bfloat16* __restrict__ qh_g, const __nv_bfloat16* __restrict__ ql_g,
    const __nv_bfloat16* __restrict__ kh_g, const __nv_bfloat16* __restrict__ kl_g,
    const __nv_bfloat16* __restrict__ vth_g, const __nv_bfloat16* __restrict__ vtl_g,
    __nv_bfloat16* __restrict__ aob)
{
    extern __shared__ char smraw[];
    const uint32_t sb0 = smem_u32(smraw);
    const uint32_t sb  = (sb0 + 1023u) & ~1023u;

    const int qt = blockIdx.x, h = blockIdx.y, bb = blockIdx.z;
    const int tid = threadIdx.x, wid = tid >> 5, lane = tid & 31;
    const size_t bh = (size_t)bb * NH + h;
    const int wq0 = qt * 128 + wid * 16;

    const int a_row = lane & 15, a_kb = (lane >> 4) * 16;
    const int b_row = (lane & 7) + ((lane >> 4) * 8);
    const int b_kb  = ((lane >> 3) & 1) * 16;

    {
        const size_t qrow0 = bh * SEQ + qt * 128;
#pragma unroll
        for (int i = 0; i < 4; i++) {
            int v = tid + i * 256; int row = v >> 3, seg = v & 7;
            uint32_t off = sw128((uint32_t)(row * 128 + seg * 16));
            cp16(sb + off,         qh_g + (qrow0 + row) * DK + seg * 8);
            cp16(sb + 16384 + off, ql_g + (qrow0 + row) * DK + seg * 8);
        }
    }

    int tiles[5]; int nt = 0;
    for (int t = qt - 2; t <= qt + 2; t++)
        if (t >= 0 && t < SEQ / 128) tiles[nt++] = t;

    attn_load_kv(sb, 0, kh_g, kl_g, vth_g, vtl_g, bh, tiles[0] * 128, tid);
    CP_COMMIT();

    uint32_t qhf[4][4], qlf[4][4];
    float o[8][4];
#pragma unroll
    for (int i = 0; i < 8; i++)
#pragma unroll
        for (int j = 0; j < 4; j++) o[i][j] = 0.f;
    float m0 = -INFINITY, m1 = -INFINITY, l0 = 0.f, l1 = 0.f;

    const int r0loc = lane >> 2;
    const int kcol  = 2 * (lane & 3);

    for (int i = 0; i < nt; i++) {
        const int buf = i & 1;
        if (i + 1 < nt) {
            attn_load_kv(sb, buf ^ 1, kh_g, kl_g, vth_g, vtl_g,
                         bh, tiles[i + 1] * 128, tid);
            CP_COMMIT();
            CP_WAIT1();
        } else {
            CP_WAIT0();
        }
        __syncthreads();

        if (i == 0) {
#pragma unroll
            for (int ks = 0; ks < 4; ks++) {
                uint32_t off = (uint32_t)((wid * 16 + a_row) * 128 + ks * 32 + a_kb);
                ldsm_x4(qhf[ks], sb + sw128(off));
                ldsm_x4(qlf[ks], sb + 16384 + sw128(off));
            }
        }

        const int t = tiles[i];
        const uint32_t kbufb = sb + ATT_SMK0 + buf * ATT_KBUF;
        const uint32_t vbufb = sb + ATT_SMV0 + buf * ATT_VBUF;
        const bool edge = (t == qt - 2) || (t == qt + 2);
        const int kt0 = t * 128;

        for (int kb = 0; kb < 8; kb++) {
            const int kblk = kt0 + kb * 16;
            if (edge) {
                if (kblk + 15 < wq0 - WIN || kblk > wq0 + 15 + WIN) continue;
            }

            float S0[4] = {0,0,0,0}, S1[4] = {0,0,0,0};
#pragma unroll
            for (int ks = 0; ks < 4; ks++) {
                uint32_t bhf[4], blf[4];
                uint32_t off = (uint32_t)((kb * 16 + b_row) * 128 + ks * 32 + b_kb);
                ldsm_x4(bhf, kbufb + sw128(off));
                ldsm_x4(blf, kbufb + 16384 + sw128(off));
                mma16816(S0, qhf[ks], bhf[0], bhf[1]);
                mma16816(S1, qhf[ks], bhf[2], bhf[3]);
                mma16816(S0, qlf[ks], bhf[0], bhf[1]);
                mma16816(S1, qlf[ks], bhf[2], bhf[3]);
                mma16816(S0, qhf[ks], blf[0], blf[1]);
                mma16816(S1, qhf[ks], blf[2], blf[3]);
            }

            if (edge) {
                const int r0 = wq0 + r0loc;
                const int d00 = (kblk + kcol) - r0 + WIN;
                S0[0] = ((unsigned)(d00    ) <= 2u*WIN) ? S0[0] : -INFINITY;
                S0[1] = ((unsigned)(d00 + 1) <= 2u*WIN) ? S0[1] : -INFINITY;
                S0[2] = ((unsigned)(d00 - 8) <= 2u*WIN) ? S0[2] : -INFINITY;
                S0[3] = ((unsigned)(d00 - 7) <= 2u*WIN) ? S0[3] : -INFINITY;
                S1[0] = ((unsigned)(d00 + 8) <= 2u*WIN) ? S1[0] : -INFINITY;
                S1[1] = ((unsigned)(d00 + 9) <= 2u*WIN) ? S1[1] : -INFINITY;
                S1[2] = ((unsigned)(d00    ) <= 2u*WIN) ? S1[2] : -INFINITY;
                S1[3] = ((unsigned)(d00 + 1) <= 2u*WIN) ? S1[3] : -INFINITY;
            }

            float rmax0 = fmaxf(fmaxf(S0[0], S0[1]), fmaxf(S1[0], S1[1]));
            float rmax1 = fmaxf(fmaxf(S0[2], S0[3]), fmaxf(S1[2], S1[3]));
            rmax0 = fmaxf(rmax0, __shfl_xor_sync(0xffffffffu, rmax0, 1));
            rmax0 = fmaxf(rmax0, __shfl_xor_sync(0xffffffffu, rmax0, 2));
            rmax1 = fmaxf(rmax1, __shfl_xor_sync(0xffffffffu, rmax1, 1));
            rmax1 = fmaxf(rmax1, __shfl_xor_sync(0xffffffffu, rmax1, 2));

            float mn0 = fmaxf(m0, rmax0), mn1 = fmaxf(m1, rmax1);
            float c0 = __expf(fminf(m0 - mn0, 0.f));
            float c1 = __expf(fminf(m1 - mn1, 0.f));
            m0 = mn0; m1 = mn1;
            l0 *= c0; l1 *= c1;
#pragma unroll
            for (int ob = 0; ob < 8; ob++) {
                o[ob][0] *= c0; o[ob][1] *= c0;
                o[ob][2] *= c1; o[ob][3] *= c1;
            }

            float p[8];
            p[0] = __expf(fmaxf(S0[0] - m0, -80.f));
            p[1] = __expf(fmaxf(S0[1] - m0, -80.f));
            p[2] = __expf(fmaxf(S0[2] - m1, -80.f));
            p[3] = __expf(fmaxf(S0[3] - m1, -80.f));
            p[4] = __expf(fmaxf(S1[0] - m0, -80.f));
            p[5] = __expf(fmaxf(S1[1] - m0, -80.f));
            p[6] = __expf(fmaxf(S1[2] - m1, -80.f));
            p[7] = __expf(fmaxf(S1[3] - m1, -80.f));
            l0 += p[0] + p[1] + p[4] + p[5];
            l1 += p[2] + p[3] + p[6] + p[7];

            float hi[8], lo[8];
#pragma unroll
            for (int j = 0; j < 8; j++) {
                __nv_bfloat16 hb = __float2bfloat16(p[j]);
                hi[j] = __bfloat162float(hb);
                lo[j] = p[j] - hi[j];
            }
            uint32_t pah[4], pal[4];
            pah[0] = pack2bf(hi[0], hi[1]); pah[1] = pack2bf(hi[2], hi[3]);
            pah[2] = pack2bf(hi[4], hi[5]); pah[3] = pack2bf(hi[6], hi[7]);
            pal[0] = pack2bf(lo[0], lo[1]); pal[1] = pack2bf(lo[2], lo[3]);
            pal[2] = pack2bf(lo[4], lo[5]); pal[3] = pack2bf(lo[6], lo[7]);

#pragma unroll
            for (int db = 0; db < 4; db++) {
                uint32_t vh4[4], vl4[4];
                uint32_t voff = (uint32_t)((db * 16 + b_row) * 272 + kb * 32 + b_kb);
                ldsm_x4(vh4, vbufb + voff);
                ldsm_x4(vl4, vbufb + 17408 + voff);
                mma16816(o[db*2],   pah, vh4[0], vh4[1]);
                mma16816(o[db*2],   pal, vh4[0], vh4[1]);
                mma16816(o[db*2],   pah, vl4[0], vl4[1]);
                mma16816(o[db*2+1], pah, vh4[2], vh4[3]);
                mma16816(o[db*2+1], pal, vh4[2], vh4[3]);
                mma16816(o[db*2+1], pah, vl4[2], vl4[3]);
            }
        }
        __syncthreads();
    }

    l0 += __shfl_xor_sync(0xffffffffu, l0, 1);
    l0 += __shfl_xor_sync(0xffffffffu, l0, 2);
    l1 += __shfl_xor_sync(0xffffffffu, l1, 1);
    l1 += __shfl_xor_sync(0xffffffffu, l1, 2);
    const float inv0 = 1.f / l0, inv1 = 1.f / l1;

    // epilogue: write bf16 [hi|lo] rows (K2 layout) for the output projection
    const size_t rg = (size_t)bb * SEQ + wq0 + r0loc;
    const int cb = h * DK + kcol;
#pragma unroll
    for (int db = 0; db < 8; db++) {
        const int c = cb + db * 8;
        float v00 = o[db][0] * inv0, v01 = o[db][1] * inv0;
        float v10 = o[db][2] * inv1, v11 = o[db][3] * inv1;

        __nv_bfloat16 h00 = __float2bfloat16(v00), h01 = __float2bfloat16(v01);
        __nv_bfloat16 h10 = __float2bfloat16(v10), h11 = __float2bfloat16(v11);
        __nv_bfloat16* r0p = aob + rg * K2 + c;
        __nv_bfloat16* r1p = aob + (rg + 8) * K2 + c;
        *(__nv_bfloat162*)r0p = __nv_bfloat162(h00, h01);
        *(__nv_bfloat162*)(r0p + DIM) = __nv_bfloat162(
            __float2bfloat16(v00 - __bfloat162float(h00)),
            __float2bfloat16(v01 - __bfloat162float(h01)));
        *(__nv_bfloat162*)r1p = __nv_bfloat162(h10, h11);
        *(__nv_bfloat162*)(r1p + DIM) = __nv_bfloat162(
            __float2bfloat16(v10 - __bfloat162float(h10)),
            __float2bfloat16(v11 - __bfloat162float(h11)));
    }
}

// ---------------------------------------------------------------------------
// Launch
// ---------------------------------------------------------------------------
extern "C" void kernel_launch(void* const* d_in, const int* in_sizes, int n_in,
                              void* d_out, int out_size)
{
    const float* q    = (const float*)d_in[0];
    const float* k    = (const float*)d_in[1];
    const float* v    = (const float*)d_in[2];
    const float* wq   = (const float*)d_in[3];
    const float* wk   = (const float*)d_in[4];
    const float* wv   = (const float*)d_in[5];
    const float* wo_w = (const float*)d_in[6];
    const float* wo_b = (const float*)d_in[7];
    float* outp = (float*)d_out;

    float *vp;
    float2* tbl;
    cudaGetSymbolAddress((void**)&vp, g_vp);
    cudaGetSymbolAddress((void**)&tbl, g_tbl);
    __nv_bfloat16 *qb, *kb, *vb, *aob, *wqb, *wkb, *wvb, *wob;
    cudaGetSymbolAddress((void**)&qb,  g_qb);
    cudaGetSymbolAddress((void**)&kb,  g_kb);
    cudaGetSymbolAddress((void**)&vb,  g_vb);
    cudaGetSymbolAddress((void**)&aob, g_aob);
    cudaGetSymbolAddress((void**)&wqb, g_wqb);
    cudaGetSymbolAddress((void**)&wkb, g_wkb);
    cudaGetSymbolAddress((void**)&wvb, g_wvb);
    cudaGetSymbolAddress((void**)&wob, g_wob);
    __nv_bfloat16 *qh, *ql, *kh, *kl, *vth, *vtl;
    cudaGetSymbolAddress((void**)&qh,  g_qh);
    cudaGetSymbolAddress((void**)&ql,  g_ql);
    cudaGetSymbolAddress((void**)&kh,  g_kh);
    cudaGetSymbolAddress((void**)&kl,  g_kl);
    cudaGetSymbolAddress((void**)&vth, g_vth);
    cudaGetSymbolAddress((void**)&vtl, g_vtl);

    cudaFuncSetAttribute(mma_gemm,
        cudaFuncAttributeMaxDynamicSharedMemorySize, DYN_SMEM);
    cudaFuncSetAttribute(attn2,
        cudaFuncAttributeMaxDynamicSharedMemorySize, ATT_SMEM);

    const int bigN   = MROWS * DIM;
    const int smallN = DIM * DIM;
    const int bigBlocks   = bigN / 4 / 256;
    const int smallBlocks = smallN / 4 / 256;

    // rope table (independent; issue first)
    rope_table<<<SEQ / RPT, 512>>>(tbl);

    // activation splits (q,k,v fused). q pre-scaled by 8 (exact, = sqrt(dk)).
    SplitArgs sa;
    sa.src[0] = q; sa.src[1] = k; sa.src[2] = v; sa.src[3] = nullptr;
    sa.dst[0] = qb; sa.dst[1] = kb; sa.dst[2] = vb; sa.dst[3] = nullptr;
    sa.scl[0] = 8.f; sa.scl[1] = 1.f; sa.scl[2] = 1.f; sa.scl[3] = 1.f;
    dim3 sg3(bigBlocks, 1, 3);
    split_multi<<<sg3, 256>>>(sa, bigN, DIM);

    // weight splits (wq,wk,wv,wo fused)
    SplitArgs sw;
    sw.src[0] = wq; sw.src[1] = wk; sw.src[2] = wv; sw.src[3] = wo_w;
    sw.dst[0] = wqb; sw.dst[1] = wkb; sw.dst[2] = wvb; sw.dst[3] = wob;
    sw.scl[0] = sw.scl[1] = sw.scl[2] = sw.scl[3] = 1.f;
    dim3 sg4(smallBlocks, 1, 4);
    split_multi<<<sg4, 256>>>(sw, smallN, DIM);

    // fused q/k/v projections; q/k use the register-only RoPE epilogue
    TCArgs pa;
    pa.A[0] = qb; pa.A[1] = kb; pa.A[2] = vb;
    pa.W[0] = wqb; pa.W[1] = wkb; pa.W[2] = wvb;
    pa.C[0] = nullptr; pa.C[1] = nullptr; pa.C[2] = vp;
    pa.bias[0] = pa.bias[1] = pa.bias[2] = nullptr;
    pa.H[0] = qh; pa.L[0] = ql;
    pa.H[1] = kh; pa.L[1] = kl;
    pa.H[2] = nullptr; pa.L[2] = nullptr;
    pa.tbl = tbl;
    pa.mode[0] = 1; pa.mode[1] = 1; pa.mode[2] = 0;
    dim3 g3(DIM / TN, MROWS / TM, 3);            // (8, 64, 3)
    mma_gemm<<<g3, 256, DYN_SMEM>>>(pa, DIM);

    // V^T hi/lo conversion
    dim3 vgrid(SEQ / 128, NH, BATCH);
    convert_v<<<vgrid, 256>>>(vp, vth, vtl);

    // tensor-core flash attention (writes aob hi/lo directly)
    dim3 agrid(SEQ / 128, NH, BATCH);
    attn2<<<agrid, 256, ATT_SMEM>>>(qh, ql, kh, kl, vth, vtl, aob);

    // output projection (+bias)
    TCArgs po;
    po.A[0] = aob; po.W[0] = wob; po.C[0] = outp; po.bias[0] = wo_b;
    po.A[1] = po.A[2] = nullptr; po.W[1] = po.W[2] = nullptr;
    po.C[1] = po.C[2] = nullptr; po.bias[1] = po.bias[2] = nullptr;
    po.H[0] = po.H[1] = po.H[2] = nullptr;
    po.L[0] = po.L[1] = po.L[2] = nullptr;
    po.tbl = tbl;
    po.mode[0] = po.mode[1] = po.mode[2] = 0;
    dim3 g1(DIM / TN, MROWS / TM, 1);
    mma_gemm<<<g1, 256, DYN_SMEM>>>(po, DIM);
}

// round 15
// speedup vs baseline: 1.0730x; 1.0730x over previous
#include <cuda_runtime.h>
#include <cuda_bf16.h>
#include <math.h>
#include <stdint.h>

#define BATCH 2
#define SEQ   4096
#define DIM   1024
#define NH    16
#define DK    64
#define WIN   256
#define HALF  (DIM/2)
#define MROWS (BATCH*SEQ)      // 8192
#define K2    (2*DIM)          // 2048 storage: [hi|lo]
// logical GEMM K = 3*DIM via chunk remap: [hiA|loA|hiA] x [hiW|hiW|loW]

// ---------------------------------------------------------------------------
// Scratch (allocation-free: __device__ globals)
// ---------------------------------------------------------------------------
__device__ float g_vp[MROWS*DIM];
__device__ float2 g_tbl[SEQ*HALF];                  // cos/sin table
__device__ __nv_bfloat16 g_qb [(size_t)MROWS*K2];
__device__ __nv_bfloat16 g_kb [(size_t)MROWS*K2];
__device__ __nv_bfloat16 g_vb [(size_t)MROWS*K2];
__device__ __nv_bfloat16 g_aob[(size_t)MROWS*K2];
__device__ __nv_bfloat16 g_wqb[(size_t)DIM*K2];
__device__ __nv_bfloat16 g_wkb[(size_t)DIM*K2];
__device__ __nv_bfloat16 g_wvb[(size_t)DIM*K2];
__device__ __nv_bfloat16 g_wob[(size_t)DIM*K2];
// per-head bf16 hi/lo buffers for attention
__device__ __nv_bfloat16 g_qh [(size_t)MROWS*DIM];
__device__ __nv_bfloat16 g_ql [(size_t)MROWS*DIM];
__device__ __nv_bfloat16 g_kh [(size_t)MROWS*DIM];
__device__ __nv_bfloat16 g_kl [(size_t)MROWS*DIM];
__device__ __nv_bfloat16 g_vth[(size_t)MROWS*DIM];  // V^T per head
__device__ __nv_bfloat16 g_vtl[(size_t)MROWS*DIM];

// ---------------------------------------------------------------------------
// Baseline-ISA helpers: cp.async / ldmatrix / mma.sync (no tcgen05).
// ---------------------------------------------------------------------------
__device__ __forceinline__ uint32_t smem_u32(const void* p) {
    uint32_t a;
    asm("{ .reg .u64 t; cvta.to.shared.u64 t, %1; cvt.u32.u64 %0, t; }"
        : "=r"(a) : "l"(p));
    return a;
}
__device__ __forceinline__ void cp16(uint32_t s, const void* g) {
    asm volatile("cp.async.cg.shared.global [%0], [%1], 16;" :: "r"(s), "l"(g));
}
#define CP_COMMIT() asm volatile("cp.async.commit_group;" ::: "memory")
#define CP_WAIT1()  asm volatile("cp.async.wait_group 1;"  ::: "memory")
#define CP_WAIT0()  asm volatile("cp.async.wait_group 0;"  ::: "memory")

__device__ __forceinline__ void ldsm_x4(uint32_t* r, uint32_t addr) {
    asm volatile("ldmatrix.sync.aligned.m8n8.x4.shared.b16 {%0,%1,%2,%3}, [%4];"
                 : "=r"(r[0]), "=r"(r[1]), "=r"(r[2]), "=r"(r[3]) : "r"(addr));
}
__device__ __forceinline__ void mma16816(float* c, const uint32_t* a,
                                         uint32_t b0, uint32_t b1) {
    asm volatile(
        "mma.sync.aligned.m16n8k16.row.col.f32.bf16.bf16.f32 "
        "{%0,%1,%2,%3}, {%4,%5,%6,%7}, {%8,%9}, {%0,%1,%2,%3};"
        : "+f"(c[0]), "+f"(c[1]), "+f"(c[2]), "+f"(c[3])
        : "r"(a[0]), "r"(a[1]), "r"(a[2]), "r"(a[3]), "r"(b0), "r"(b1));
}
static __device__ __forceinline__ uint32_t sw128(uint32_t off) {
    return off ^ ((off >> 3) & 0x70);
}
__device__ __forceinline__ uint32_t pack2bf(float a, float b) {
    __nv_bfloat162 t = __floats2bfloat162_rn(a, b);
    return *reinterpret_cast<uint32_t*>(&t);
}

// ---------------------------------------------------------------------------
// fp32 -> bf16 hi/lo split, multi-tensor: dst row = [hi(0..K) | lo(K..2K)]
// ---------------------------------------------------------------------------
struct SplitArgs {
    const float*   src[4];
    __nv_bfloat16* dst[4];
};

__global__ __launch_bounds__(256) void split_multi(SplitArgs a, int total, int K)
{
    const float* __restrict__ src = a.src[blockIdx.z];
    __nv_bfloat16* __restrict__ dst = a.dst[blockIdx.z];

    int i4 = blockIdx.x * blockDim.x + threadIdx.x;
    if (i4 * 4 >= total) return;
    int idx = i4 * 4;
    int row = idx / K;
    int col = idx % K;

    float4 x = *(const float4*)(src + idx);
    __nv_bfloat16 h0 = __float2bfloat16(x.x);
    __nv_bfloat16 h1 = __float2bfloat16(x.y);
    __nv_bfloat16 h2 = __float2bfloat16(x.z);
    __nv_bfloat16 h3 = __float2bfloat16(x.w);
    __nv_bfloat16 l0 = __float2bfloat16(x.x - __bfloat162float(h0));
    __nv_bfloat16 l1 = __float2bfloat16(x.y - __bfloat162float(h1));
    __nv_bfloat16 l2 = __float2bfloat16(x.z - __bfloat162float(h2));
    __nv_bfloat16 l3 = __float2bfloat16(x.w - __bfloat162float(h3));

    size_t base = (size_t)row * (2 * K);
    __nv_bfloat162* d0 = (__nv_bfloat162*)(dst + base + col);
    d0[0] = __nv_bfloat162(h0, h1); d0[1] = __nv_bfloat162(h2, h3);
    __nv_bfloat162* d1 = (__nv_bfloat162*)(dst + base + K + col);
    d1[0] = __nv_bfloat162(l0, l1); d1[1] = __nv_bfloat162(l2, l3);
}

// ---------------------------------------------------------------------------
// Tensor-core GEMM via mma.sync (R12 core + R13 smem RoPE epilogue; measured
// best 840.8us total). CTA 128x128, 8 warps, warp tile 64x32, K=3072 remap,
// 3-stage cp.async pipeline, fragment double-buffering, 2 CTAs/SM.
// mode 1/2 (q/k): paired-column B-row remap + smem RoPE + hi/lo epilogue.
// ---------------------------------------------------------------------------
#define TM 128
#define TN 128
#define KC 64
#define NCHUNK ((3*DIM)/KC)    // 48
#define SMBUF  32768           // 16KB A + 16KB B per stage
#define DYN_SMEM (3*SMBUF + 1024)

struct TCArgs {
    const __nv_bfloat16* A[3];
    const __nv_bfloat16* W[3];
    float*               C[3];
    const float*         bias[3];
    __nv_bfloat16*       H[3];
    __nv_bfloat16*       L[3];
    const float2*        tbl;
    int                  mode[3];   // 0 plain, 1 q-rope(x8), 2 k-rope
};

__device__ __forceinline__ void cp_chunk(
    uint32_t smA, uint32_t smB,
    const __nv_bfloat16* __restrict__ A, const __nv_bfloat16* __restrict__ W,
    int m0, int n0, int kcol, int tid, int rope)
{
    const int ka = (kcol < 2048) ? kcol : kcol - 2048;  // A: hi,lo,hi
    const int kw = (kcol < 1024) ? kcol : kcol - 1024;  // W: hi,hi,lo
#pragma unroll
    for (int i = 0; i < 4; i++) {
        int v = tid + i * 256;
        int row = v >> 3, vc = v & 7;
        cp16(smA + sw128(row * 128 + vc * 16),
             A + (size_t)(m0 + row) * K2 + ka + vc * 8);
    }
#pragma unroll
    for (int i = 0; i < 4; i++) {
        int v = tid + i * 256;
        int row = v >> 3, vc = v & 7;
        // rope mode: B-rows are W rows [n0/2, n0/2+64) U [n0/2+512, n0/2+576)
        int wrow = rope ? ((n0 >> 1) + row + (row >> 6) * 448) : (n0 + row);
        cp16(smB + sw128(row * 128 + vc * 16),
             W + (size_t)wrow * K2 + kw + vc * 8);
    }
}

__global__ __launch_bounds__(256, 2) void mma_gemm(TCArgs args, int N)
{
    extern __shared__ char smraw[];
    const uint32_t sb0 = smem_u32(smraw);
    const uint32_t sb  = (sb0 + 1023u) & ~1023u;
    char* smcp = smraw + (sb - sb0);

    const int z = blockIdx.z;
    const __nv_bfloat16* __restrict__ A = args.A[z];
    const __nv_bfloat16* __restrict__ W = args.W[z];
    const int mode = args.mode[z];
    const int rope = (mode != 0);

    const int tid  = threadIdx.x;
    const int wid  = tid >> 5;
    const int lane = tid & 31;
    const int wm   = wid & 1;
    const int wn   = wid >> 1;
    const int m0 = blockIdx.y * TM;
    const int n0 = blockIdx.x * TN;

    const int a_row = lane & 15;
    const int a_kb  = (lane >> 4) * 16;
    const int b_row = (lane & 7) + ((lane >> 4) * 8);
    const int b_kb  = ((lane >> 3) & 1) * 16;

    float acc[4][4][4];
#pragma unroll
    for (int i = 0; i < 4; i++)
#pragma unroll
        for (int j = 0; j < 4; j++)
#pragma unroll
            for (int t = 0; t < 4; t++) acc[i][j][t] = 0.f;

    cp_chunk(sb, sb + 16384, A, W, m0, n0, 0, tid, rope);
    CP_COMMIT();
    cp_chunk(sb + SMBUF, sb + SMBUF + 16384, A, W, m0, n0, KC, tid, rope);
    CP_COMMIT();

    uint32_t af[2][4][4], bf2[2][8];

    for (int i = 0; i < NCHUNK; i++) {
        if (i + 1 < NCHUNK) { CP_WAIT1(); } else { CP_WAIT0(); }
        __syncthreads();

        if (i + 2 < NCHUNK) {
            const uint32_t st = sb + ((i + 2) % 3) * SMBUF;
            cp_chunk(st, st + 16384, A, W, m0, n0, (i + 2) * KC, tid, rope);
            CP_COMMIT();
        }

        const uint32_t smA = sb + (i % 3) * SMBUF;
        const uint32_t smB = smA + 16384;

        {
#pragma unroll
            for (int mt = 0; mt < 4; mt++) {
                uint32_t off = (uint32_t)(wm * 64 + mt * 16 + a_row) * 128 + a_kb;
                ldsm_x4(af[0][mt], smA + sw128(off));
            }
#pragma unroll
            for (int bt = 0; bt < 2; bt++) {
                uint32_t off = (uint32_t)(wn * 32 + bt * 16 + b_row) * 128 + b_kb;
                ldsm_x4(bf2[0] + bt * 4, smB + sw128(off));
            }
        }
#pragma unroll
        for (int ks = 0; ks < 4; ks++) {
            const int cur = ks & 1;
            if (ks < 3) {
                const int nxt = cur ^ 1;
#pragma unroll
                for (int mt = 0; mt < 4; mt++) {
                    uint32_t off = (uint32_t)(wm * 64 + mt * 16 + a_row) * 128
                                 + (ks + 1) * 32 + a_kb;
                    ldsm_x4(af[nxt][mt], smA + sw128(off));
                }
#pragma unroll
                for (int bt = 0; bt < 2; bt++) {
                    uint32_t off = (uint32_t)(wn * 32 + bt * 16 + b_row) * 128
                                 + (ks + 1) * 32 + b_kb;
                    ldsm_x4(bf2[nxt] + bt * 4, smB + sw128(off));
                }
            }
#pragma unroll
            for (int mt = 0; mt < 4; mt++)
#pragma unroll
                for (int nt = 0; nt < 4; nt++) {
                    const int bi = (nt >> 1) * 4 + (nt & 1) * 2;
                    mma16816(acc[mt][nt], af[cur][mt], bf2[cur][bi], bf2[cur][bi + 1]);
                }
        }
    }

    if (mode == 0) {
        float* __restrict__ C = args.C[z];
        const float* bias = args.bias[z];
        const int rbase = m0 + wm * 64 + (lane >> 2);
        const int cbase = n0 + wn * 32 + 2 * (lane & 3);
#pragma unroll
        for (int mt = 0; mt < 4; mt++) {
#pragma unroll
            for (int nt = 0; nt < 4; nt++) {
                const int r = rbase + mt * 16;
                const int c = cbase + nt * 8;
                float2 v0 = { acc[mt][nt][0], acc[mt][nt][1] };
                float2 v1 = { acc[mt][nt][2], acc[mt][nt][3] };
                if (bias) {
                    v0.x += bias[c]; v0.y += bias[c + 1];
                    v1.x += bias[c]; v1.y += bias[c + 1];
                }
                *(float2*)(C + (size_t)r * N + c)       = v0;
                *(float2*)(C + (size_t)(r + 8) * N + c) = v1;
            }
        }
        return;
    }

    // ---- fused RoPE + per-head hi/lo epilogue (mode 1 = q, 2 = k) ----
    __syncthreads();
    float* sm = (float*)smcp;            // 128 x 132 fp32 tile
    {
        const int rl = wm * 64 + (lane >> 2);
        const int cl = wn * 32 + 2 * (lane & 3);
#pragma unroll
        for (int mt = 0; mt < 4; mt++) {
#pragma unroll
            for (int nt = 0; nt < 4; nt++) {
                const int r = rl + mt * 16;
                const int c = cl + nt * 8;
                *(float2*)(sm + r * 132 + c)       =
                    make_float2(acc[mt][nt][0], acc[mt][nt][1]);
                *(float2*)(sm + (r + 8) * 132 + c) =
                    make_float2(acc[mt][nt][2], acc[mt][nt][3]);
            }
        }
    }
    __syncthreads();

    __nv_bfloat16* __restrict__ H = args.H[z];
    __nv_bfloat16* __restrict__ L = args.L[z];
    const float2* __restrict__ tbl = args.tbl;
    const float scale = (mode == 1) ? 8.f : 1.f;
    const int n0c = blockIdx.x * 64;
    const int h1  = blockIdx.x;

    for (int it = 0; it < 16; it++) {
        const int p   = tid + it * 256;
        const int rr  = p >> 5;
        const int lcp = (p & 31) * 2;
        const int grow = m0 + rr;
        const int s    = grow & (SEQ - 1);
        const int bidx = grow >> 12;

        float4 t = *(const float4*)(tbl + (size_t)s * HALF + n0c + lcp);
        float x10 = sm[rr * 132 + lcp],      x11 = sm[rr * 132 + lcp + 1];
        float x20 = sm[rr * 132 + lcp + 64], x21 = sm[rr * 132 + lcp + 65];

        float v10 = (x10 * t.x - x20 * t.y) * scale;
        float v20 = (x10 * t.y + x20 * t.x) * scale;
        float v11 = (x11 * t.z - x21 * t.w) * scale;
        float v21 = (x11 * t.w + x21 * t.z) * scale;

        __nv_bfloat16 a0 = __float2bfloat16(v10), a1 = __float2bfloat16(v11);
        __nv_bfloat16 b0 = __float2bfloat16(v20), b1 = __float2bfloat16(v21);

        const size_t d1 = ((size_t)(bidx * NH + h1)     * SEQ + s) * DK + lcp;
        const size_t d2 = ((size_t)(bidx * NH + h1 + 8) * SEQ + s) * DK + lcp;
        *(__nv_bfloat162*)(H + d1) = __nv_bfloat162(a0, a1);
        *(__nv_bfloat162*)(L + d1) = __nv_bfloat162(
            __float2bfloat16(v10 - __bfloat162float(a0)),
            __float2bfloat16(v11 - __bfloat162float(a1)));
        *(__nv_bfloat162*)(H + d2) = __nv_bfloat162(b0, b1);
        *(__nv_bfloat162*)(L + d2) = __nv_bfloat162(
            __float2bfloat16(v20 - __bfloat162float(b0)),
            __float2bfloat16(v21 - __bfloat162float(b1)));
    }
}

// ---------------------------------------------------------------------------
// RoPE cos/sin table
// ---------------------------------------------------------------------------
#define RPT 16
__global__ __launch_bounds__(512) void rope_table(float2* __restrict__ tbl)
{
    const int e    = threadIdx.x;
    const int pgrp = blockIdx.x;

    const double inv = exp(-((double)e / (double)HALF) * 9.2103403719761827);

#pragma unroll 4
    for (int i = 0; i < RPT; i++) {
        const int pos = pgrp * RPT + i;
        const double ang = (double)pos * inv;
        const double kq  = rint(ang * 0.15915494309189533);
        const float  r   = (float)(ang - kq * 6.2831853071795865);
        float s, c;
        sincosf(r, &s, &c);
        tbl[(size_t)pos * HALF + e] = make_float2(c, s);
    }
}

// ---------------------------------------------------------------------------
// convert_v: vp -> V^T bf16 hi/lo
// ---------------------------------------------------------------------------
__global__ __launch_bounds__(256) void convert_v(
    const float* __restrict__ vp,
    __nv_bfloat16* __restrict__ vth, __nv_bfloat16* __restrict__ vtl)
{
    __shared__ float tile[128][65];
    const int st = blockIdx.x, hh = blockIdx.y, b = blockIdx.z;
    const int tid = threadIdx.x;

#pragma unroll
    for (int i = 0; i < 8; i++) {
        int v = tid + i * 256;
        int s = v >> 4, dseg = v & 15;
        float4 x = *(const float4*)(vp
            + ((size_t)(b * SEQ) + st * 128 + s) * DIM + hh * 64 + dseg * 4);
        tile[s][dseg*4+0] = x.x; tile[s][dseg*4+1] = x.y;
        tile[s][dseg*4+2] = x.z; tile[s][dseg*4+3] = x.w;
    }
    __syncthreads();

#pragma unroll
    for (int i = 0; i < 4; i++) {
        int v = tid + i * 256;
        int d = v >> 4, kseg = v & 15;
        __nv_bfloat16 hi8[8], lo8[8];
#pragma unroll
        for (int j = 0; j < 8; j++) {
            float x = tile[kseg * 8 + j][d];
            hi8[j] = __float2bfloat16(x);
            lo8[j] = __float2bfloat16(x - __bfloat162float(hi8[j]));
        }
        size_t dst = (((size_t)(b * NH + hh)) * DK + d) * SEQ + st * 128 + kseg * 8;
        *(uint4*)(vth + dst) = *(uint4*)hi8;
        *(uint4*)(vtl + dst) = *(uint4*)lo8;
    }
}

// ---------------------------------------------------------------------------
// Flash attention on tensor cores. Single-buffered K/V (99KB smem) with
// __launch_bounds__(256,2) -> 2 CTAs/SM; cross-CTA overlap replaces the
// intra-CTA double buffer (R11 occupancy lesson). Epilogue writes aob hi/lo.
// ---------------------------------------------------------------------------
#define AT_Q 0
#define AT_K 32768
#define AT_V 65536
#define ATT_SMEM (100352 + 1024)

__device__ __forceinline__ void attn_load_kv(
    uint32_t sb,
    const __nv_bfloat16* __restrict__ kh, const __nv_bfloat16* __restrict__ kl,
    const __nv_bfloat16* __restrict__ vth, const __nv_bfloat16* __restrict__ vtl,
    size_t bh, int kbase, int tid)
{
    const uint32_t kdst = sb + AT_K;
    const size_t krow0 = bh * SEQ + kbase;
#pragma unroll
    for (int i = 0; i < 4; i++) {
        int v = tid + i * 256; int row = v >> 3, seg = v & 7;
        uint32_t off = sw128((uint32_t)(row * 128 + seg * 16));
        cp16(kdst + off,         kh + (krow0 + row) * DK + seg * 8);
        cp16(kdst + 16384 + off, kl + (krow0 + row) * DK + seg * 8);
    }
    const uint32_t vdst = sb + AT_V;
    const size_t vrow0 = bh * DK;
#pragma unroll
    for (int i = 0; i < 4; i++) {
        int v = tid + i * 256; int d = v >> 4, seg = v & 15;
        uint32_t off = (uint32_t)(d * 272 + seg * 16);
        cp16(vdst + off,         vth + (vrow0 + d) * SEQ + kbase + seg * 8);
        cp16(vdst + 17408 + off, vtl + (vrow0 + d) * SEQ + kbase + seg * 8);
    }
}

__global__ __launch_bounds__(256, 2) void attn2(
    const __nv_bfloat16* __restrict__ qh_g, const __nv_bfloat16* __restrict__ ql_g,
    const __nv_bfloat16* __restrict__ kh_g, const __nv_bfloat16* __restrict__ kl_g,
    const __nv_bfloat16* __restrict__ vth_g, const __nv_bfloat16* __restrict__ vtl_g,
    __nv_bfloat16* __restrict__ aob)
{
    extern __shared__ char smraw[];
    const uint32_t sb0 = smem_u32(smraw);
    const uint32_t sb  = (sb0 + 1023u) & ~1023u;

    const int qt = blockIdx.x, h = blockIdx.y, bb = blockIdx.z;
    const int tid = threadIdx.x, wid = tid >> 5, lane = tid & 31;
    const size_t bh = (size_t)bb * NH + h;
    const int wq0 = qt * 128 + wid * 16;

    const int a_row = lane & 15, a_kb = (lane >> 4) * 16;
    const int b_row = (lane & 7) + ((lane >> 4) * 8);
    const int b_kb  = ((lane >> 3) & 1) * 16;

    // Q tile (hi/lo) -> smem (once)
    {
        const size_t qrow0 = bh * SEQ + qt * 128;
#pragma unroll
        for (int i = 0; i < 4; i++) {
            int v = tid + i * 256; int row = v >> 3, seg = v & 7;
            uint32_t off = sw128((uint32_t)(row * 128 + seg * 16));
            cp16(sb + AT_Q + off,         qh_g + (qrow0 + row) * DK + seg * 8);
            cp16(sb + AT_Q + 16384 + off, ql_g + (qrow0 + row) * DK + seg * 8);
        }
    }

    int tiles[5]; int nt = 0;
    for (int t = qt - 2; t <= qt + 2; t++)
        if (t >= 0 && t < SEQ / 128) tiles[nt++] = t;

    uint32_t qhf[4][4], qlf[4][4];
    float o[8][4];
#pragma unroll
    for (int i = 0; i < 8; i++)
#pragma unroll
        for (int j = 0; j < 4; j++) o[i][j] = 0.f;
    float m0 = -INFINITY, m1 = -INFINITY, l0 = 0.f, l1 = 0.f;

    const int r0loc = lane >> 2;
    const int kcol  = 2 * (lane & 3);

    const uint32_t kbufb = sb + AT_K;
    const uint32_t vbufb = sb + AT_V;

    for (int i = 0; i < nt; i++) {
        if (i > 0) __syncthreads();     // previous tile's compute done
        attn_load_kv(sb, kh_g, kl_g, vth_g, vtl_g, bh, tiles[i] * 128, tid);
        CP_COMMIT();
        CP_WAIT0();
        __syncthreads();

        if (i == 0) {
#pragma unroll
            for (int ks = 0; ks < 4; ks++) {
                uint32_t off = (uint32_t)((wid * 16 + a_row) * 128 + ks * 32 + a_kb);
                ldsm_x4(qhf[ks], sb + AT_Q + sw128(off));
                ldsm_x4(qlf[ks], sb + AT_Q + 16384 + sw128(off));
            }
        }

        const int t = tiles[i];
        const bool edge = (t == qt - 2) || (t == qt + 2);
        const int kt0 = t * 128;

        for (int kb = 0; kb < 8; kb++) {
            const int kblk = kt0 + kb * 16;
            if (edge) {
                if (kblk + 15 < wq0 - WIN || kblk > wq0 + 15 + WIN) continue;
            }

            float S0[4] = {0,0,0,0}, S1[4] = {0,0,0,0};
#pragma unroll
            for (int ks = 0; ks < 4; ks++) {
                uint32_t bhf[4], blf[4];
                uint32_t off = (uint32_t)((kb * 16 + b_row) * 128 + ks * 32 + b_kb);
                ldsm_x4(bhf, kbufb + sw128(off));
                ldsm_x4(blf, kbufb + 16384 + sw128(off));
                mma16816(S0, qhf[ks], bhf[0], bhf[1]);
                mma16816(S1, qhf[ks], bhf[2], bhf[3]);
                mma16816(S0, qlf[ks], bhf[0], bhf[1]);
                mma16816(S1, qlf[ks], bhf[2], bhf[3]);
                mma16816(S0, qhf[ks], blf[0], blf[1]);
                mma16816(S1, qhf[ks], blf[2], blf[3]);
            }

            if (edge) {
                const int r0 = wq0 + r0loc;
                const int d00 = (kblk + kcol) - r0 + WIN;
                S0[0] = ((unsigned)(d00    ) <= 2u*WIN) ? S0[0] : -INFINITY;
                S0[1] = ((unsigned)(d00 + 1) <= 2u*WIN) ? S0[1] : -INFINITY;
                S0[2] = ((unsigned)(d00 - 8) <= 2u*WIN) ? S0[2] : -INFINITY;
                S0[3] = ((unsigned)(d00 - 7) <= 2u*WIN) ? S0[3] : -INFINITY;
                S1[0] = ((unsigned)(d00 + 8) <= 2u*WIN) ? S1[0] : -INFINITY;
                S1[1] = ((unsigned)(d00 + 9) <= 2u*WIN) ? S1[1] : -INFINITY;
                S1[2] = ((unsigned)(d00    ) <= 2u*WIN) ? S1[2] : -INFINITY;
                S1[3] = ((unsigned)(d00 + 1) <= 2u*WIN) ? S1[3] : -INFINITY;
            }

            float rmax0 = fmaxf(fmaxf(S0[0], S0[1]), fmaxf(S1[0], S1[1]));
            float rmax1 = fmaxf(fmaxf(S0[2], S0[3]), fmaxf(S1[2], S1[3]));
            rmax0 = fmaxf(rmax0, __shfl_xor_sync(0xffffffffu, rmax0, 1));
            rmax0 = fmaxf(rmax0, __shfl_xor_sync(0xffffffffu, rmax0, 2));
            rmax1 = fmaxf(rmax1, __shfl_xor_sync(0xffffffffu, rmax1, 1));
            rmax1 = fmaxf(rmax1, __shfl_xor_sync(0xffffffffu, rmax1, 2));

            float mn0 = fmaxf(m0, rmax0), mn1 = fmaxf(m1, rmax1);
            float c0 = __expf(fminf(m0 - mn0, 0.f));
            float c1 = __expf(fminf(m1 - mn1, 0.f));
            m0 = mn0; m1 = mn1;
            l0 *= c0; l1 *= c1;
#pragma unroll
            for (int ob = 0; ob < 8; ob++) {
                o[ob][0] *= c0; o[ob][1] *= c0;
                o[ob][2] *= c1; o[ob][3] *= c1;
            }

            float p[8];
            p[0] = __expf(fmaxf(S0[0] - m0, -80.f));
            p[1] = __expf(fmaxf(S0[1] - m0, -80.f));
            p[2] = __expf(fmaxf(S0[2] - m1, -80.f));
            p[3] = __expf(fmaxf(S0[3] - m1, -80.f));
            p[4] = __expf(fmaxf(S1[0] - m0, -80.f));
            p[5] = __expf(fmaxf(S1[1] - m0, -80.f));
            p[6] = __expf(fmaxf(S1[2] - m1, -80.f));
            p[7] = __expf(fmaxf(S1[3] - m1, -80.f));
            l0 += p[0] + p[1] + p[4] + p[5];
            l1 += p[2] + p[3] + p[6] + p[7];

            float hi[8], lo[8];
#pragma unroll
            for (int j = 0; j < 8; j++) {
                __nv_bfloat16 hb = __float2bfloat16(p[j]);
                hi[j] = __bfloat162float(hb);
                lo[j] = p[j] - hi[j];
            }
            uint32_t pah[4], pal[4];
            pah[0] = pack2bf(hi[0], hi[1]); pah[1] = pack2bf(hi[2], hi[3]);
            pah[2] = pack2bf(hi[4], hi[5]); pah[3] = pack2bf(hi[6], hi[7]);
            pal[0] = pack2bf(lo[0], lo[1]); pal[1] = pack2bf(lo[2], lo[3]);
            pal[2] = pack2bf(lo[4], lo[5]); pal[3] = pack2bf(lo[6], lo[7]);

#pragma unroll
            for (int db = 0; db < 4; db++) {
                uint32_t vh4[4], vl4[4];
                uint32_t voff = (uint32_t)((db * 16 + b_row) * 272 + kb * 32 + b_kb);
                ldsm_x4(vh4, vbufb + voff);
                ldsm_x4(vl4, vbufb + 17408 + voff);
                mma16816(o[db*2],   pah, vh4[0], vh4[1]);
                mma16816(o[db*2],   pal, vh4[0], vh4[1]);
                mma16816(o[db*2],   pah, vl4[0], vl4[1]);
                mma16816(o[db*2+1], pah, vh4[2], vh4[3]);
                mma16816(o[db*2+1], pal, vh4[2], vh4[3]);
                mma16816(o[db*2+1], pah, vl4[2], vl4[3]);
            }
        }
    }

    l0 += __shfl_xor_sync(0xffffffffu, l0, 1);
    l0 += __shfl_xor_sync(0xffffffffu, l0, 2);
    l1 += __shfl_xor_sync(0xffffffffu, l1, 1);
    l1 += __shfl_xor_sync(0xffffffffu, l1, 2);
    const float inv0 = 1.f / l0, inv1 = 1.f / l1;

    const size_t rg = (size_t)bb * SEQ + wq0 + r0loc;
    const int cb = h * DK + kcol;
#pragma unroll
    for (int db = 0; db < 8; db++) {
        const int c = cb + db * 8;
        float v00 = o[db][0] * inv0, v01 = o[db][1] * inv0;
        float v10 = o[db][2] * inv1, v11 = o[db][3] * inv1;

        __nv_bfloat16 h00 = __float2bfloat16(v00), h01 = __float2bfloat16(v01);
        __nv_bfloat16 h10 = __float2bfloat16(v10), h11 = __float2bfloat16(v11);
        __nv_bfloat16* r0p = aob + rg * K2 + c;
        __nv_bfloat16* r1p = aob + (rg + 8) * K2 + c;
        *(__nv_bfloat162*)r0p = __nv_bfloat162(h00, h01);
        *(__nv_bfloat162*)(r0p + DIM) = __nv_bfloat162(
            __float2bfloat16(v00 - __bfloat162float(h00)),
            __float2bfloat16(v01 - __bfloat162float(h01)));
        *(__nv_bfloat162*)r1p = __nv_bfloat162(h10, h11);
        *(__nv_bfloat162*)(r1p + DIM) = __nv_bfloat162(
            __float2bfloat16(v10 - __bfloat162float(h10)),
            __float2bfloat16(v11 - __bfloat162float(h11)));
    }
}

// ---------------------------------------------------------------------------
// Launch
// ---------------------------------------------------------------------------
extern "C" void kernel_launch(void* const* d_in, const int* in_sizes, int n_in,
                              void* d_out, int out_size)
{
    const float* q    = (const float*)d_in[0];
    const float* k    = (const float*)d_in[1];
    const float* v    = (const float*)d_in[2];
    const float* wq   = (const float*)d_in[3];
    const float* wk   = (const float*)d_in[4];
    const float* wv   = (const float*)d_in[5];
    const float* wo_w = (const float*)d_in[6];
    const float* wo_b = (const float*)d_in[7];
    float* outp = (float*)d_out;

    float *vp;
    float2* tbl;
    cudaGetSymbolAddress((void**)&vp, g_vp);
    cudaGetSymbolAddress((void**)&tbl, g_tbl);
    __nv_bfloat16 *qb, *kb, *vb, *aob, *wqb, *wkb, *wvb, *wob;
    cudaGetSymbolAddress((void**)&qb,  g_qb);
    cudaGetSymbolAddress((void**)&kb,  g_kb);
    cudaGetSymbolAddress((void**)&vb,  g_vb);
    cudaGetSymbolAddress((void**)&aob, g_aob);
    cudaGetSymbolAddress((void**)&wqb, g_wqb);
    cudaGetSymbolAddress((void**)&wkb, g_wkb);
    cudaGetSymbolAddress((void**)&wvb, g_wvb);
    cudaGetSymbolAddress((void**)&wob, g_wob);
    __nv_bfloat16 *qh, *ql, *kh, *kl, *vth, *vtl;
    cudaGetSymbolAddress((void**)&qh,  g_qh);
    cudaGetSymbolAddress((void**)&ql,  g_ql);
    cudaGetSymbolAddress((void**)&kh,  g_kh);
    cudaGetSymbolAddress((void**)&kl,  g_kl);
    cudaGetSymbolAddress((void**)&vth, g_vth);
    cudaGetSymbolAddress((void**)&vtl, g_vtl);

    cudaFuncSetAttribute(mma_gemm,
        cudaFuncAttributeMaxDynamicSharedMemorySize, DYN_SMEM);
    cudaFuncSetAttribute(attn2,
        cudaFuncAttributeMaxDynamicSharedMemorySize, ATT_SMEM);

    const int bigN   = MROWS * DIM;
    const int smallN = DIM * DIM;
    const int bigBlocks   = bigN / 4 / 256;
    const int smallBlocks = smallN / 4 / 256;

    // rope table (independent; issue first)
    rope_table<<<SEQ / RPT, 512>>>(tbl);

    // activation splits (q,k,v fused)
    SplitArgs sa;
    sa.src[0] = q; sa.src[1] = k; sa.src[2] = v; sa.src[3] = nullptr;
    sa.dst[0] = qb; sa.dst[1] = kb; sa.dst[2] = vb; sa.dst[3] = nullptr;
    dim3 sg3(bigBlocks, 1, 3);
    split_multi<<<sg3, 256>>>(sa, bigN, DIM);

    // weight splits (wq,wk,wv,wo fused)
    SplitArgs sw;
    sw.src[0] = wq; sw.src[1] = wk; sw.src[2] = wv; sw.src[3] = wo_w;
    sw.dst[0] = wqb; sw.dst[1] = wkb; sw.dst[2] = wvb; sw.dst[3] = wob;
    dim3 sg4(smallBlocks, 1, 4);
    split_multi<<<sg4, 256>>>(sw, smallN, DIM);

    // fused q/k/v projections; q/k use the fused RoPE + hi/lo epilogue
    TCArgs pa;
    pa.A[0] = qb; pa.A[1] = kb; pa.A[2] = vb;
    pa.W[0] = wqb; pa.W[1] = wkb; pa.W[2] = wvb;
    pa.C[0] = nullptr; pa.C[1] = nullptr; pa.C[2] = vp;
    pa.bias[0] = pa.bias[1] = pa.bias[2] = nullptr;
    pa.H[0] = qh; pa.L[0] = ql;
    pa.H[1] = kh; pa.L[1] = kl;
    pa.H[2] = nullptr; pa.L[2] = nullptr;
    pa.tbl = tbl;
    pa.mode[0] = 1; pa.mode[1] = 2; pa.mode[2] = 0;
    dim3 g3(DIM / TN, MROWS / TM, 3);            // (8, 64, 3)
    mma_gemm<<<g3, 256, DYN_SMEM>>>(pa, DIM);

    // V^T hi/lo conversion
    dim3 vgrid(SEQ / 128, NH, BATCH);
    convert_v<<<vgrid, 256>>>(vp, vth, vtl);

    // tensor-core flash attention (2 CTAs/SM; writes aob hi/lo directly)
    dim3 agrid(SEQ / 128, NH, BATCH);
    attn2<<<agrid, 256, ATT_SMEM>>>(qh, ql, kh, kl, vth, vtl, aob);

    // output projection (+bias)
    TCArgs po;
    po.A[0] = aob; po.W[0] = wob; po.C[0] = outp; po.bias[0] = wo_b;
    po.A[1] = po.A[2] = nullptr; po.W[1] = po.W[2] = nullptr;
    po.C[1] = po.C[2] = nullptr; po.bias[1] = po.bias[2] = nullptr;
    po.H[0] = po.H[1] = po.H[2] = nullptr;
    po.L[0] = po.L[1] = po.L[2] = nullptr;
    po.tbl = tbl;
    po.mode[0] = po.mode[1] = po.mode[2] = 0;
    dim3 g1(DIM / TN, MROWS / TM, 1);
    mma_gemm<<<g1, 256, DYN_SMEM>>>(po, DIM);
}